// round 7
// baseline (speedup 1.0000x reference)
#include <cuda_runtime.h>
#include <cuda_bf16.h>
#include <cstdint>

#define DIMN 128
#define NMAX 100000
#define EMAX 600000
#define GRIDP 148          // persistent grid for k_final

// ---------------- scratch (device globals; no allocation allowed) -------------
__device__ float    g_q[NMAX * DIMN];
__device__ float    g_k[NMAX * DIMN];
__device__ float    g_v[NMAX * DIMN];
__device__ float    g_agg[NMAX * DIMN];
__device__ int      g_cnt[NMAX];
__device__ int      g_off[NMAX + 1];
__device__ int      g_pos[NMAX];
__device__ int      g_esrc[EMAX];
__device__ __nv_bfloat16 g_wh[4 * DIMN * DIMN];   // bf16 hi of Wq,Wk,Wv,Wp
__device__ __nv_bfloat16 g_wl[4 * DIMN * DIMN];   // bf16 residual

// ---------------- smem layout (bytes, dynamic) --------------------------------
// bf16 tiles [128 rows][128 cols]: 16 chunks of 16B per row,
// phys_chunk = chunk ^ (row & 7)  (conflict-free ldmatrix)
#define SM_AH    0
#define SM_AL    32768
#define SM_W0    65536      // W buffer 0: hi at +0, lo at +32768
#define SM_W1    131072     // k_qkv: W buffer 1 (double buffer)
#define SM_QKV_TOT 196608

#define SM_STG   131072     // k_final: fp32 staging tile (64KB)
#define SM_FIN_TOT 196608

// ---------------- helpers ------------------------------------------------------
__device__ __forceinline__ uint32_t smem_u32(const void* p) {
    uint32_t a;
    asm("{ .reg .u64 t; cvta.to.shared.u64 t, %1; cvt.u32.u64 %0, t; }" : "=r"(a) : "l"(p));
    return a;
}
__device__ __forceinline__ uint32_t sw_off(int row, int chunk) {
    return (uint32_t)(row * 256 + ((chunk ^ (row & 7)) << 4));
}
__device__ __forceinline__ void cp16(uint32_t saddr, const void* g, bool pred) {
    int sz = pred ? 16 : 0;
    asm volatile("cp.async.cg.shared.global [%0], [%1], 16, %2;"
                 :: "r"(saddr), "l"(g), "r"(sz) : "memory");
}
#define CP_COMMIT() asm volatile("cp.async.commit_group;" ::: "memory")
#define CP_WAIT0()  asm volatile("cp.async.wait_group 0;" ::: "memory")

__device__ __forceinline__ void ldsm4a(uint32_t* r, uint32_t base, int mrow0, int kchunk) {
    int lane = threadIdx.x & 31;
    uint32_t a = base + sw_off(mrow0 + (lane & 15), kchunk + (lane >> 4));
    asm volatile("ldmatrix.sync.aligned.m8n8.x4.shared.b16 {%0,%1,%2,%3}, [%4];"
        : "=r"(r[0]), "=r"(r[1]), "=r"(r[2]), "=r"(r[3]) : "r"(a));
}
__device__ __forceinline__ void ldsm4b(uint32_t* r, uint32_t base, int nrow0, int kchunk) {
    int lane = threadIdx.x & 31;
    uint32_t a = base + sw_off(nrow0 + ((lane >> 4) << 3) + (lane & 7),
                               kchunk + ((lane >> 3) & 1));
    asm volatile("ldmatrix.sync.aligned.m8n8.x4.shared.b16 {%0,%1,%2,%3}, [%4];"
        : "=r"(r[0]), "=r"(r[1]), "=r"(r[2]), "=r"(r[3]) : "r"(a));
}
__device__ __forceinline__ void mma16816(float* c, const uint32_t* a, const uint32_t* b) {
    asm volatile("mma.sync.aligned.m16n8k16.row.col.f32.bf16.bf16.f32 "
        "{%0,%1,%2,%3}, {%4,%5,%6,%7}, {%8,%9}, {%0,%1,%2,%3};"
        : "+f"(c[0]), "+f"(c[1]), "+f"(c[2]), "+f"(c[3])
        : "r"(a[0]), "r"(a[1]), "r"(a[2]), "r"(a[3]), "r"(b[0]), "r"(b[1]));
}
__device__ __forceinline__ unsigned pack_bf2(float x, float y) {
    __nv_bfloat16 a = __float2bfloat16(x), b = __float2bfloat16(y);
    return (unsigned)__bfloat16_as_ushort(a) | ((unsigned)__bfloat16_as_ushort(b) << 16);
}

// convert 128-row fp32 tile (from GLOBAL) -> Ah/Al smem (512 threads)
__device__ __forceinline__ void x_to_smem(const float* __restrict__ X, int row0, int N,
                                          char* sm) {
    for (int idx = threadIdx.x; idx < 2048; idx += 512) {
        int row = idx >> 4, c = idx & 15;
        int grow = row0 + row;
        float v[8];
        if (grow < N) {
            float4 v0 = ((const float4*)X)[(size_t)grow * 32 + c * 2];
            float4 v1 = ((const float4*)X)[(size_t)grow * 32 + c * 2 + 1];
            v[0] = v0.x; v[1] = v0.y; v[2] = v0.z; v[3] = v0.w;
            v[4] = v1.x; v[5] = v1.y; v[6] = v1.z; v[7] = v1.w;
        } else {
#pragma unroll
            for (int j = 0; j < 8; j++) v[j] = 0.f;
        }
        uint4 hi, lo;
        float r[8];
#pragma unroll
        for (int j = 0; j < 8; j++) {
            __nv_bfloat16 hb = __float2bfloat16(v[j]);
            r[j] = v[j] - __bfloat162float(hb);
        }
        hi.x = pack_bf2(v[0], v[1]); hi.y = pack_bf2(v[2], v[3]);
        hi.z = pack_bf2(v[4], v[5]); hi.w = pack_bf2(v[6], v[7]);
        lo.x = pack_bf2(r[0], r[1]); lo.y = pack_bf2(r[2], r[3]);
        lo.z = pack_bf2(r[4], r[5]); lo.w = pack_bf2(r[6], r[7]);
        uint32_t o = sw_off(row, c);
        *(uint4*)(sm + SM_AH + o) = hi;
        *(uint4*)(sm + SM_AL + o) = lo;
    }
}

// load pre-split bf16 weight o into W smem buffer at byte offset wbase (LDG path)
__device__ __forceinline__ void w_to_smem(int o, char* sm, int wbase) {
    const uint4* wh = (const uint4*)&g_wh[o * DIMN * DIMN];
    const uint4* wl = (const uint4*)&g_wl[o * DIMN * DIMN];
    for (int idx = threadIdx.x; idx < 2048; idx += 512) {
        int row = idx >> 4, c = idx & 15;
        uint32_t ofs = sw_off(row, c);
        *(uint4*)(sm + wbase + ofs) = wh[idx];
        *(uint4*)(sm + wbase + 32768 + ofs) = wl[idx];
    }
}

// fused 3-term split GEMM; warp tile 16(m) x 64(n); c_[8][4]
__device__ __forceinline__ void compute_tile(uint32_t sb, uint32_t wbase,
                                             float c_[8][4], int wm, int wn) {
#pragma unroll
    for (int kk = 0; kk < 8; kk++) {
        uint32_t ah[4], al[4], bh[4][4], bl[4][4];
        ldsm4a(ah, sb + SM_AH, wm * 16, kk * 2);
        ldsm4a(al, sb + SM_AL, wm * 16, kk * 2);
#pragma unroll
        for (int p = 0; p < 4; p++) {
            ldsm4b(bh[p], sb + wbase,         wn * 64 + p * 16, kk * 2);
            ldsm4b(bl[p], sb + wbase + 32768, wn * 64 + p * 16, kk * 2);
        }
#pragma unroll
        for (int p = 0; p < 4; p++) {
            mma16816(c_[2 * p],     ah, &bh[p][0]);
            mma16816(c_[2 * p + 1], ah, &bh[p][2]);
            mma16816(c_[2 * p],     ah, &bl[p][0]);
            mma16816(c_[2 * p + 1], ah, &bl[p][2]);
            mma16816(c_[2 * p],     al, &bh[p][0]);
            mma16816(c_[2 * p + 1], al, &bh[p][2]);
        }
    }
}

// ---------------- weight split prep + cnt zero ----------------------------------
__global__ void __launch_bounds__(256)
k_prep(const float* __restrict__ Wq, const float* __restrict__ Wk,
       const float* __restrict__ Wv, const float* __restrict__ Wp, int N) {
    int i = blockIdx.x * 256 + threadIdx.x;
    if (i < 4 * DIMN * DIMN) {
        const float* srcs[4] = {Wq, Wk, Wv, Wp};
        float w = srcs[i >> 14][i & 16383];
        __nv_bfloat16 hb = __float2bfloat16(w);
        g_wh[i] = hb;
        g_wl[i] = __float2bfloat16(w - __bfloat162float(hb));
    }
    for (int j = i; j < N; j += gridDim.x * 256) g_cnt[j] = 0;
}

// ---------------- edge binning: histogram / scan / scatter ----------------------
__global__ void __launch_bounds__(256)
k_hist(const int* __restrict__ edges, int E) {
    int e = blockIdx.x * 256 + threadIdx.x;
    if (e < E) atomicAdd(&g_cnt[__ldg(&edges[E + e])], 1);
}

__global__ void __launch_bounds__(1024)
k_scan(int N, int E) {
    __shared__ int part[1024];
    int t = threadIdx.x;
    int chunk = (N + 1023) / 1024;
    int lo = t * chunk, hi = min(lo + chunk, N);
    int s = 0;
    for (int i = lo; i < hi; i++) s += g_cnt[i];
    part[t] = s;
    __syncthreads();
    for (int d = 1; d < 1024; d <<= 1) {
        int val = (t >= d) ? part[t - d] : 0;
        __syncthreads();
        part[t] += val;
        __syncthreads();
    }
    int base = (t == 0) ? 0 : part[t - 1];
    for (int i = lo; i < hi; i++) {
        g_off[i] = base;
        g_pos[i] = base;
        base += g_cnt[i];
    }
    if (t == 1023) g_off[N] = E;
}

__global__ void __launch_bounds__(256)
k_scatter(const int* __restrict__ edges, int E) {
    int e = blockIdx.x * 256 + threadIdx.x;
    if (e >= E) return;
    int s  = __ldg(&edges[e]);
    int dn = __ldg(&edges[E + e]);
    int p = atomicAdd(&g_pos[dn], 1);
    g_esrc[p] = s;
}

// ---------------- fused QKV GEMM (unchanged core) -------------------------------
__global__ void __launch_bounds__(512, 1)
k_qkv(const float* __restrict__ h, int N) {
    extern __shared__ char sm[];
    uint32_t sb = smem_u32(sm);
    const int tid = threadIdx.x;
    const int row0 = blockIdx.x * 128;
    const int lane = tid & 31, w = tid >> 5, wm = w >> 1, wn = w & 1;
    const int gid = lane >> 2, tig = lane & 3;

    // zero agg slice (needed only for zero-degree nodes; k_edge2 overwrites others)
    for (int idx = tid; idx < 128 * 32; idx += 512) {
        int r = idx >> 5;
        if (row0 + r < N)
            ((float4*)g_agg)[(size_t)(row0 + r) * 32 + (idx & 31)] = make_float4(0, 0, 0, 0);
    }

    x_to_smem(h, row0, N, sm);
    w_to_smem(0, sm, SM_W0);
    __syncthreads();

#pragma unroll
    for (int o = 0; o < 3; o++) {
        uint32_t wbase = (o & 1) ? SM_W1 : SM_W0;
        if (o < 2) w_to_smem(o + 1, sm, (o & 1) ? SM_W0 : SM_W1);  // prefetch next W

        float c_[8][4];
#pragma unroll
        for (int nt = 0; nt < 8; nt++)
#pragma unroll
            for (int j = 0; j < 4; j++) c_[nt][j] = 0.f;

        compute_tile(sb, wbase, c_, wm, wn);

        float* outp = (o == 0) ? g_q : ((o == 1) ? g_k : g_v);
        int r_lo = row0 + wm * 16 + gid;
#pragma unroll
        for (int nt = 0; nt < 8; nt++) {
            int col = wn * 64 + nt * 8 + tig * 2;
            if (r_lo < N)
                *(float2*)&outp[(size_t)r_lo * DIMN + col] =
                    make_float2(c_[nt][0], c_[nt][1]);
            if (r_lo + 8 < N)
                *(float2*)&outp[(size_t)(r_lo + 8) * DIMN + col] =
                    make_float2(c_[nt][2], c_[nt][3]);
        }
        __syncthreads();
    }
}

// ---------------- edge aggregation: one warp per dst node -----------------------
// agg[d] = sum_e exp(q[d].k[src_e]/sqrt(dim)) * v[src_e] / (sum_e exp + 1e-9)
// No segment-max (scores ~N(0,1); clip is overflow guard). Non-atomic single write.
__global__ void __launch_bounds__(256)
k_edge2(int N) {
    int d = blockIdx.x * 8 + (threadIdx.x >> 5);
    if (d >= N) return;
    int lane = threadIdx.x & 31;

    int off = __ldg(&g_off[d]);
    int end = __ldg(&g_off[d + 1]);
    if (off == end) return;                  // agg stays zero (matches alpha=0)

    float4 q4 = ((const float4*)g_q)[(size_t)d * 32 + lane];

    float sum = 0.f;
    float4 acc = make_float4(0.f, 0.f, 0.f, 0.f);

    // depth-2 software pipeline over this node's edges
    int s_cur = __ldg(&g_esrc[off]);
    float4 k4 = ((const float4*)g_k)[(size_t)s_cur * 32 + lane];
    float4 v4 = ((const float4*)g_v)[(size_t)s_cur * 32 + lane];

    for (int j = off; j < end; j++) {
        float4 ck = k4, cv = v4;
        if (j + 1 < end) {
            int s_nx = __ldg(&g_esrc[j + 1]);
            k4 = ((const float4*)g_k)[(size_t)s_nx * 32 + lane];
            v4 = ((const float4*)g_v)[(size_t)s_nx * 32 + lane];
        }
        float dot = q4.x * ck.x + q4.y * ck.y + q4.z * ck.z + q4.w * ck.w;
#pragma unroll
        for (int o = 16; o > 0; o >>= 1) dot += __shfl_xor_sync(0xffffffffu, dot, o);
        float sc = fminf(fmaxf(dot * 0.08838834764831845f, -60.f), 60.f);
        float ex = __expf(sc);
        sum += ex;
        acc.x += ex * cv.x; acc.y += ex * cv.y;
        acc.z += ex * cv.z; acc.w += ex * cv.w;
    }

    float inv = 1.0f / (sum + 1e-9f);
    ((float4*)g_agg)[(size_t)d * 32 + lane] =
        make_float4(acc.x * inv, acc.y * inv, acc.z * inv, acc.w * inv);
}

// ---------------- persistent final GEMM -----------------------------------------
// out = relu(agg @ Wp^T + bp + h); agg already normalized by k_edge2
__global__ void __launch_bounds__(512, 1)
k_final(const float* __restrict__ h, const float* __restrict__ bp,
        float* __restrict__ out, int N, int ntiles) {
    extern __shared__ char sm[];
    uint32_t sb = smem_u32(sm);
    const int tid = threadIdx.x;
    const int lane = tid & 31, w = tid >> 5, wm = w >> 1, wn = w & 1;
    const int gid = lane >> 2, tig = lane & 3;

    // W (hi+lo) via cp.async, once per CTA
    {
        const char* wh = (const char*)&g_wh[3 * DIMN * DIMN];
        const char* wl = (const char*)&g_wl[3 * DIMN * DIMN];
#pragma unroll
        for (int j = 0; j < 4; j++) {
            int idx = tid + j * 512;
            int row = idx >> 4, c = idx & 15;
            uint32_t ofs = sw_off(row, c);
            cp16(sb + SM_W0 + ofs,         wh + idx * 16, true);
            cp16(sb + SM_W0 + 32768 + ofs, wl + idx * 16, true);
        }
    }

    // prologue: stage first tile's fp32 agg
    int t0 = blockIdx.x;
    if (t0 < ntiles) {
#pragma unroll
        for (int j = 0; j < 8; j++) {
            int idx = tid + j * 512;
            int row = idx >> 5, c = idx & 31;
            int grow = t0 * 128 + row;
            cp16(sb + SM_STG + row * 512 + c * 16,
                 (const char*)g_agg + ((size_t)grow * 128 + c * 4) * 4, grow < N);
        }
    }
    CP_COMMIT();

    for (int t = blockIdx.x; t < ntiles; t += GRIDP) {
        CP_WAIT0();
        __syncthreads();                              // staging holds tile t; W ready

        const int row0 = t * 128;
        for (int idx = tid; idx < 2048; idx += 512) {
            int row = idx >> 4, c = idx & 15;
            float4 v0 = *(const float4*)(sm + SM_STG + row * 512 + c * 32);
            float4 v1 = *(const float4*)(sm + SM_STG + row * 512 + c * 32 + 16);
            float v[8] = {v0.x, v0.y, v0.z, v0.w, v1.x, v1.y, v1.z, v1.w};
            uint4 hi, lo;
            float r[8];
#pragma unroll
            for (int j = 0; j < 8; j++) {
                __nv_bfloat16 hb = __float2bfloat16(v[j]);
                r[j] = v[j] - __bfloat162float(hb);
            }
            hi.x = pack_bf2(v[0], v[1]); hi.y = pack_bf2(v[2], v[3]);
            hi.z = pack_bf2(v[4], v[5]); hi.w = pack_bf2(v[6], v[7]);
            lo.x = pack_bf2(r[0], r[1]); lo.y = pack_bf2(r[2], r[3]);
            lo.z = pack_bf2(r[4], r[5]); lo.w = pack_bf2(r[6], r[7]);
            uint32_t o = sw_off(row, c);
            *(uint4*)(sm + SM_AH + o) = hi;
            *(uint4*)(sm + SM_AL + o) = lo;
        }
        __syncthreads();                              // AH/AL ready; staging free

        int tn = t + GRIDP;
        if (tn < ntiles) {
#pragma unroll
            for (int j = 0; j < 8; j++) {
                int idx = tid + j * 512;
                int row = idx >> 5, c = idx & 31;
                int grow = tn * 128 + row;
                cp16(sb + SM_STG + row * 512 + c * 16,
                     (const char*)g_agg + ((size_t)grow * 128 + c * 4) * 4, grow < N);
            }
        }
        CP_COMMIT();

        float c_[8][4];
#pragma unroll
        for (int nt = 0; nt < 8; nt++)
#pragma unroll
            for (int j = 0; j < 4; j++) c_[nt][j] = 0.f;

        compute_tile(sb, SM_W0, c_, wm, wn);

        int r_lo = row0 + wm * 16 + gid;
#pragma unroll
        for (int nt = 0; nt < 8; nt++) {
            int col = wn * 64 + nt * 8 + tig * 2;
            float2 b = *(const float2*)&bp[col];
            if (r_lo < N) {
                float2 hh = __ldg((const float2*)&h[(size_t)r_lo * DIMN + col]);
                float2 v;
                v.x = fmaxf(c_[nt][0] + b.x + hh.x, 0.f);
                v.y = fmaxf(c_[nt][1] + b.y + hh.y, 0.f);
                *(float2*)&out[(size_t)r_lo * DIMN + col] = v;
            }
            if (r_lo + 8 < N) {
                float2 hh = __ldg((const float2*)&h[(size_t)(r_lo + 8) * DIMN + col]);
                float2 v;
                v.x = fmaxf(c_[nt][2] + b.x + hh.x, 0.f);
                v.y = fmaxf(c_[nt][3] + b.y + hh.y, 0.f);
                *(float2*)&out[(size_t)(r_lo + 8) * DIMN + col] = v;
            }
        }
    }
}

// ---------------- launch -------------------------------------------------------
extern "C" void kernel_launch(void* const* d_in, const int* in_sizes, int n_in,
                              void* d_out, int out_size) {
    const float* h     = (const float*)d_in[0];
    const int*   edges = (const int*)d_in[1];
    const float* Wq    = (const float*)d_in[2];
    const float* Wk    = (const float*)d_in[3];
    const float* Wv    = (const float*)d_in[4];
    const float* Wp    = (const float*)d_in[5];
    const float* bp    = (const float*)d_in[6];
    float*       out   = (float*)d_out;

    int N  = in_sizes[0] / DIMN;
    int E  = in_sizes[1] / 2;
    int NB = (N + 127) / 128;

    cudaFuncSetAttribute(k_qkv,   cudaFuncAttributeMaxDynamicSharedMemorySize, SM_QKV_TOT);
    cudaFuncSetAttribute(k_final, cudaFuncAttributeMaxDynamicSharedMemorySize, SM_FIN_TOT);

    k_prep<<<(4 * DIMN * DIMN + 255) / 256, 256>>>(Wq, Wk, Wv, Wp, N);
    k_hist<<<(E + 255) / 256, 256>>>(edges, E);
    k_scan<<<1, 1024>>>(N, E);
    k_scatter<<<(E + 255) / 256, 256>>>(edges, E);
    k_qkv<<<NB, 512, SM_QKV_TOT>>>(h, N);
    k_edge2<<<(N + 7) / 8, 256>>>(N);
    k_final<<<GRIDP, 512, SM_FIN_TOT>>>(h, bp, out, N, NB);
}

// round 8
// speedup vs baseline: 1.5036x; 1.5036x over previous
#include <cuda_runtime.h>
#include <cuda_bf16.h>
#include <cstdint>

#define DIMN 128
#define NMAX 100000
#define EMAX 600000

// ---------------- scratch (device globals; no allocation allowed) -------------
__device__ float    g_q[NMAX * DIMN];
__device__ float    g_k[NMAX * DIMN];
__device__ float    g_u[NMAX * DIMN];     // u = h @ (Wp@Wv)^T
__device__ float    g_agg[NMAX * DIMN];
__device__ float    g_sum[NMAX];
__device__ float    g_wpv[DIMN * DIMN];   // P = Wp @ Wv (fp32)
__device__ __nv_bfloat16 g_wh[3 * DIMN * DIMN];   // bf16 hi of Wq, Wk, P
__device__ __nv_bfloat16 g_wl[3 * DIMN * DIMN];   // bf16 residual

// ---------------- smem layout (bytes, dynamic) --------------------------------
// bf16 tiles [128 rows][128 cols]: 16 chunks of 16B per row,
// phys_chunk = chunk ^ (row & 7)  (conflict-free ldmatrix)
#define SM_AH    0
#define SM_AL    32768
#define SM_W0    65536      // W buffer 0: hi at +0, lo at +32768
#define SM_W1    131072     // W buffer 1 (double buffer)
#define SM_QKV_TOT 196608

// ---------------- helpers ------------------------------------------------------
__device__ __forceinline__ uint32_t smem_u32(const void* p) {
    uint32_t a;
    asm("{ .reg .u64 t; cvta.to.shared.u64 t, %1; cvt.u32.u64 %0, t; }" : "=r"(a) : "l"(p));
    return a;
}
__device__ __forceinline__ uint32_t sw_off(int row, int chunk) {
    return (uint32_t)(row * 256 + ((chunk ^ (row & 7)) << 4));
}
__device__ __forceinline__ void ldsm4a(uint32_t* r, uint32_t base, int mrow0, int kchunk) {
    int lane = threadIdx.x & 31;
    uint32_t a = base + sw_off(mrow0 + (lane & 15), kchunk + (lane >> 4));
    asm volatile("ldmatrix.sync.aligned.m8n8.x4.shared.b16 {%0,%1,%2,%3}, [%4];"
        : "=r"(r[0]), "=r"(r[1]), "=r"(r[2]), "=r"(r[3]) : "r"(a));
}
__device__ __forceinline__ void ldsm4b(uint32_t* r, uint32_t base, int nrow0, int kchunk) {
    int lane = threadIdx.x & 31;
    uint32_t a = base + sw_off(nrow0 + ((lane >> 4) << 3) + (lane & 7),
                               kchunk + ((lane >> 3) & 1));
    asm volatile("ldmatrix.sync.aligned.m8n8.x4.shared.b16 {%0,%1,%2,%3}, [%4];"
        : "=r"(r[0]), "=r"(r[1]), "=r"(r[2]), "=r"(r[3]) : "r"(a));
}
__device__ __forceinline__ void mma16816(float* c, const uint32_t* a, const uint32_t* b) {
    asm volatile("mma.sync.aligned.m16n8k16.row.col.f32.bf16.bf16.f32 "
        "{%0,%1,%2,%3}, {%4,%5,%6,%7}, {%8,%9}, {%0,%1,%2,%3};"
        : "+f"(c[0]), "+f"(c[1]), "+f"(c[2]), "+f"(c[3])
        : "r"(a[0]), "r"(a[1]), "r"(a[2]), "r"(a[3]), "r"(b[0]), "r"(b[1]));
}
__device__ __forceinline__ unsigned pack_bf2(float x, float y) {
    __nv_bfloat16 a = __float2bfloat16(x), b = __float2bfloat16(y);
    return (unsigned)__bfloat16_as_ushort(a) | ((unsigned)__bfloat16_as_ushort(b) << 16);
}

// convert 128-row fp32 tile (from GLOBAL) -> Ah/Al smem (512 threads)
__device__ __forceinline__ void x_to_smem(const float* __restrict__ X, int row0, int N,
                                          char* sm) {
    for (int idx = threadIdx.x; idx < 2048; idx += 512) {
        int row = idx >> 4, c = idx & 15;
        int grow = row0 + row;
        float v[8];
        if (grow < N) {
            float4 v0 = ((const float4*)X)[(size_t)grow * 32 + c * 2];
            float4 v1 = ((const float4*)X)[(size_t)grow * 32 + c * 2 + 1];
            v[0] = v0.x; v[1] = v0.y; v[2] = v0.z; v[3] = v0.w;
            v[4] = v1.x; v[5] = v1.y; v[6] = v1.z; v[7] = v1.w;
        } else {
#pragma unroll
            for (int j = 0; j < 8; j++) v[j] = 0.f;
        }
        uint4 hi, lo;
        float r[8];
#pragma unroll
        for (int j = 0; j < 8; j++) {
            __nv_bfloat16 hb = __float2bfloat16(v[j]);
            r[j] = v[j] - __bfloat162float(hb);
        }
        hi.x = pack_bf2(v[0], v[1]); hi.y = pack_bf2(v[2], v[3]);
        hi.z = pack_bf2(v[4], v[5]); hi.w = pack_bf2(v[6], v[7]);
        lo.x = pack_bf2(r[0], r[1]); lo.y = pack_bf2(r[2], r[3]);
        lo.z = pack_bf2(r[4], r[5]); lo.w = pack_bf2(r[6], r[7]);
        uint32_t o = sw_off(row, c);
        *(uint4*)(sm + SM_AH + o) = hi;
        *(uint4*)(sm + SM_AL + o) = lo;
    }
}

// load pre-split bf16 weight o into W smem buffer at byte offset wbase
__device__ __forceinline__ void w_to_smem(int o, char* sm, int wbase) {
    const uint4* wh = (const uint4*)&g_wh[o * DIMN * DIMN];
    const uint4* wl = (const uint4*)&g_wl[o * DIMN * DIMN];
    for (int idx = threadIdx.x; idx < 2048; idx += 512) {
        int row = idx >> 4, c = idx & 15;
        uint32_t ofs = sw_off(row, c);
        *(uint4*)(sm + wbase + ofs) = wh[idx];
        *(uint4*)(sm + wbase + 32768 + ofs) = wl[idx];
    }
}

// fused 3-term split GEMM; warp tile 16(m) x 64(n); c_[8][4]
__device__ __forceinline__ void compute_tile(uint32_t sb, uint32_t wbase,
                                             float c_[8][4], int wm, int wn) {
#pragma unroll
    for (int kk = 0; kk < 8; kk++) {
        uint32_t ah[4], al[4], bh[4][4], bl[4][4];
        ldsm4a(ah, sb + SM_AH, wm * 16, kk * 2);
        ldsm4a(al, sb + SM_AL, wm * 16, kk * 2);
#pragma unroll
        for (int p = 0; p < 4; p++) {
            ldsm4b(bh[p], sb + wbase,         wn * 64 + p * 16, kk * 2);
            ldsm4b(bl[p], sb + wbase + 32768, wn * 64 + p * 16, kk * 2);
        }
#pragma unroll
        for (int p = 0; p < 4; p++) {
            mma16816(c_[2 * p],     ah, &bh[p][0]);
            mma16816(c_[2 * p + 1], ah, &bh[p][2]);
            mma16816(c_[2 * p],     ah, &bl[p][0]);
            mma16816(c_[2 * p + 1], ah, &bl[p][2]);
            mma16816(c_[2 * p],     al, &bh[p][0]);
            mma16816(c_[2 * p + 1], al, &bh[p][2]);
        }
    }
}

// ---------------- P = Wp @ Wv (fp32, tiny) --------------------------------------
// P[i][j] = sum_k Wp[i][k] * Wv[k][j]; grid 128 blocks (one row each), 128 thr
__global__ void __launch_bounds__(128)
k_wpv(const float* __restrict__ Wp, const float* __restrict__ Wv) {
    __shared__ float wp_row[DIMN];
    int i = blockIdx.x, j = threadIdx.x;
    wp_row[j] = Wp[i * DIMN + j];
    __syncthreads();
    float acc = 0.f;
#pragma unroll 8
    for (int k = 0; k < DIMN; k++)
        acc += wp_row[k] * Wv[k * DIMN + j];
    g_wpv[i * DIMN + j] = acc;
}

// ---------------- weight split prep (Wq, Wk, P) ---------------------------------
__global__ void __launch_bounds__(256)
k_prep(const float* __restrict__ Wq, const float* __restrict__ Wk) {
    int i = blockIdx.x * 256 + threadIdx.x;
    if (i >= 3 * DIMN * DIMN) return;
    const float* srcs[3] = {Wq, Wk, g_wpv};
    float w = srcs[i >> 14][i & 16383];
    __nv_bfloat16 hb = __float2bfloat16(w);
    g_wh[i] = hb;
    g_wl[i] = __float2bfloat16(w - __bfloat162float(hb));
}

// ---------------- fused Q/K/U GEMM + state init ---------------------------------
__global__ void __launch_bounds__(512, 1)
k_qkv(const float* __restrict__ h, int N) {
    extern __shared__ char sm[];
    uint32_t sb = smem_u32(sm);
    const int tid = threadIdx.x;
    const int row0 = blockIdx.x * 128;
    const int lane = tid & 31, w = tid >> 5, wm = w >> 1, wn = w & 1;
    const int gid = lane >> 2, tig = lane & 3;

    if (tid < 128 && row0 + tid < N) g_sum[row0 + tid] = 0.f;
    for (int idx = tid; idx < 128 * 32; idx += 512) {
        int r = idx >> 5;
        if (row0 + r < N)
            ((float4*)g_agg)[(size_t)(row0 + r) * 32 + (idx & 31)] = make_float4(0, 0, 0, 0);
    }

    x_to_smem(h, row0, N, sm);
    w_to_smem(0, sm, SM_W0);
    __syncthreads();

#pragma unroll
    for (int o = 0; o < 3; o++) {
        uint32_t wbase = (o & 1) ? SM_W1 : SM_W0;
        if (o < 2) w_to_smem(o + 1, sm, (o & 1) ? SM_W0 : SM_W1);  // prefetch next W

        float c_[8][4];
#pragma unroll
        for (int nt = 0; nt < 8; nt++)
#pragma unroll
            for (int j = 0; j < 4; j++) c_[nt][j] = 0.f;

        compute_tile(sb, wbase, c_, wm, wn);

        float* outp = (o == 0) ? g_q : ((o == 1) ? g_k : g_u);
        int r_lo = row0 + wm * 16 + gid;
#pragma unroll
        for (int nt = 0; nt < 8; nt++) {
            int col = wn * 64 + nt * 8 + tig * 2;
            if (r_lo < N)
                *(float2*)&outp[(size_t)r_lo * DIMN + col] =
                    make_float2(c_[nt][0], c_[nt][1]);
            if (r_lo + 8 < N)
                *(float2*)&outp[(size_t)(r_lo + 8) * DIMN + col] =
                    make_float2(c_[nt][2], c_[nt][3]);
        }
        __syncthreads();
    }
}

// ---------------- fused edge phase: 4 edges per warp (R6-proven) ----------------
// ex = exp(q[dst].k[src]/sqrt(d)); sum[dst] += ex; agg[dst] += ex*u[src].
// No segment-max (scores ~N(0,1); clip is overflow guard only).
__global__ void __launch_bounds__(256)
k_edge(const int* __restrict__ edges, int E) {
    int warp = blockIdx.x * 8 + (threadIdx.x >> 5);
    int e0 = warp * 4;
    if (e0 >= E) return;
    int lane = threadIdx.x & 31;

    int idx = 0;
    if (lane < 4) { int e = e0 + lane;     if (e < E) idx = __ldg(&edges[e]); }
    else if (lane < 8) { int e = e0 + lane - 4; if (e < E) idx = __ldg(&edges[E + e]); }

    int s[4], dn[4];
    bool ok[4];
#pragma unroll
    for (int j = 0; j < 4; j++) {
        s[j]  = __shfl_sync(0xffffffffu, idx, j);
        dn[j] = __shfl_sync(0xffffffffu, idx, 4 + j);
        ok[j] = (e0 + j < E);
    }

    float4 qv[4], kv[4], uv[4];
#pragma unroll
    for (int j = 0; j < 4; j++) {
        qv[j] = ((const float4*)g_q)[(size_t)dn[j] * 32 + lane];
        kv[j] = ((const float4*)g_k)[(size_t)s[j] * 32 + lane];
        uv[j] = ((const float4*)g_u)[(size_t)s[j] * 32 + lane];
    }

#pragma unroll
    for (int j = 0; j < 4; j++) {
        float dot = qv[j].x * kv[j].x + qv[j].y * kv[j].y
                  + qv[j].z * kv[j].z + qv[j].w * kv[j].w;
#pragma unroll
        for (int o = 16; o > 0; o >>= 1) dot += __shfl_xor_sync(0xffffffffu, dot, o);
        float sc = fminf(fmaxf(dot * 0.08838834764831845f, -60.f), 60.f);
        float ex = __expf(sc);
        if (ok[j]) {
            if (lane == 0)
                asm volatile("red.relaxed.gpu.global.add.f32 [%0], %1;"
                             :: "l"(&g_sum[dn[j]]), "f"(ex) : "memory");
            float* dst = &g_agg[(size_t)dn[j] * DIMN + lane * 4];
            asm volatile(
                "red.relaxed.gpu.global.add.v4.f32 [%0], {%1, %2, %3, %4};"
                :: "l"(dst), "f"(uv[j].x * ex), "f"(uv[j].y * ex),
                   "f"(uv[j].z * ex), "f"(uv[j].w * ex)
                : "memory");
        }
    }
}

// ---------------- epilogue: out = relu(agg/(sum+eps) + bp + h) -------------------
// one warp per node row; fully streaming
__global__ void __launch_bounds__(256)
k_norm(const float* __restrict__ h, const float* __restrict__ bp,
       float* __restrict__ out, int N) {
    int r = blockIdx.x * 8 + (threadIdx.x >> 5);
    if (r >= N) return;
    int lane = threadIdx.x & 31;

    float inv = 1.0f / (__ldg(&g_sum[r]) + 1e-9f);
    float4 a = ((const float4*)g_agg)[(size_t)r * 32 + lane];
    float4 hh = __ldg(&((const float4*)h)[(size_t)r * 32 + lane]);
    float4 b = __ldg(&((const float4*)bp)[lane]);
    float4 v;
    v.x = fmaxf(a.x * inv + b.x + hh.x, 0.f);
    v.y = fmaxf(a.y * inv + b.y + hh.y, 0.f);
    v.z = fmaxf(a.z * inv + b.z + hh.z, 0.f);
    v.w = fmaxf(a.w * inv + b.w + hh.w, 0.f);
    ((float4*)out)[(size_t)r * 32 + lane] = v;
}

// ---------------- launch -------------------------------------------------------
extern "C" void kernel_launch(void* const* d_in, const int* in_sizes, int n_in,
                              void* d_out, int out_size) {
    const float* h     = (const float*)d_in[0];
    const int*   edges = (const int*)d_in[1];
    const float* Wq    = (const float*)d_in[2];
    const float* Wk    = (const float*)d_in[3];
    const float* Wv    = (const float*)d_in[4];
    const float* Wp    = (const float*)d_in[5];
    const float* bp    = (const float*)d_in[6];
    float*       out   = (float*)d_out;

    int N  = in_sizes[0] / DIMN;
    int E  = in_sizes[1] / 2;
    int NB = (N + 127) / 128;

    cudaFuncSetAttribute(k_qkv, cudaFuncAttributeMaxDynamicSharedMemorySize, SM_QKV_TOT);

    k_wpv<<<DIMN, DIMN>>>(Wp, Wv);
    k_prep<<<(3 * DIMN * DIMN + 255) / 256, 256>>>(Wq, Wk);
    k_qkv<<<NB, 512, SM_QKV_TOT>>>(h, N);
    k_edge<<<(E + 31) / 32, 256>>>(edges, E);
    k_norm<<<(N + 7) / 8, 256>>>(h, bp, out, N);
}